// round 6
// baseline (speedup 1.0000x reference)
#include <cuda_runtime.h>

#define NROWS 8192
#define CCOLS 2048
#define BINS  30
#define TOTF  8192.0f  /* tot = max(N,1) */

// Scratch (no cudaMalloc allowed): histogram counts + prefolded weight table.
__device__ unsigned int g_counts[BINS * CCOLS];
__device__ float        g_wfac[BINS * CCOLS];

// bin = clip(floor(30*|sigmoid(p)-t|), 0, 29)
// |sigmoid(p)-t| = sigmoid(s) with s = p*(1-2t) for t in {0,1}
// 30*sigmoid(s) = 15*tanh(s/2) + 15  -> single MUFU.TANH
__device__ __forceinline__ int bin_of(float p, float t) {
    float s = p * fmaf(-2.0f, t, 1.0f);
    float u;
    asm("tanh.approx.f32 %0, %1;" : "=f"(u) : "f"(0.5f * s));
    int b = __float2int_rd(fmaf(15.0f, u, 15.0f));
    return min(max(b, 0), BINS - 1);
}

// ---------------------------------------------------------------- K0: zero scratch + out
__global__ void zero_kernel(float* out) {
    int i = blockIdx.x * blockDim.x + threadIdx.x;
    if (i < BINS * CCOLS) g_counts[i] = 0u;
    if (i == 0) out[0] = 0.0f;
}

// ---------------------------------------------------------------- K1: per-column histogram
// Block: 256 threads, each owns one column -> conflict-free private shared counters.
// Grid: (CCOLS/256, NROWS/ROWS_PER_BLK)
#define ROWS_PER_BLK 128
__global__ __launch_bounds__(256) void hist_kernel(const float* __restrict__ preds,
                                                   const int*   __restrict__ targets) {
    __shared__ unsigned int sh[BINS][256];
    const int tid = threadIdx.x;
    const int c   = blockIdx.x * 256 + tid;
    const int r0  = blockIdx.y * ROWS_PER_BLK;

#pragma unroll
    for (int b = 0; b < BINS; b++) sh[b][tid] = 0u;
    // no __syncthreads needed: each thread only ever touches sh[*][tid]

    const float* pp = preds   + (size_t)r0 * CCOLS + c;
    const int*   tp = targets + (size_t)r0 * CCOLS + c;

#pragma unroll 4
    for (int r = 0; r < ROWS_PER_BLK; r++) {
        float p = pp[(size_t)r * CCOLS];
        int   t = tp[(size_t)r * CCOLS];
        int   b = bin_of(p, (float)t);
        sh[b][tid]++;
    }

#pragma unroll
    for (int b = 0; b < BINS; b++) {
        unsigned int v = sh[b][tid];
        if (v) atomicAdd(&g_counts[b * CCOLS + c], v);
    }
}

// ---------------------------------------------------------------- K2: fold weights
// wfac[b][c] = TOT / (0.75*acc[b][c] + 0.25*cnt[b][c]) / max(n[c],1)
__global__ void wfac_kernel(const float* __restrict__ acc_sum) {
    int c = blockIdx.x * blockDim.x + threadIdx.x;
    if (c >= CCOLS) return;
    float accn[BINS];
    int n = 0;
#pragma unroll
    for (int b = 0; b < BINS; b++) {
        unsigned int cnt = g_counts[b * CCOLS + c];
        n += (cnt >= 1u) ? 1 : 0;
        accn[b] = fmaf(0.25f, (float)cnt, 0.75f * acc_sum[b * CCOLS + c]);
    }
    float nf = (float)max(n, 1);
#pragma unroll
    for (int b = 0; b < BINS; b++) {
        g_wfac[b * CCOLS + c] = TOTF / (accn[b] * nf);
    }
}

// ---------------------------------------------------------------- K3: weighted BCE sum
__device__ __forceinline__ float elem_term(float p, int ti, int c) {
    float t = (float)ti;
    int   b = bin_of(p, t);                        // identical code path as K1
    float w = __ldg(&g_wfac[b * CCOLS + c]);       // 245 KB table, L2-resident
    // bce = softplus(p) - p*t = max(p,0) + log(1+exp(-|p|)) - p*t
    float ap  = fabsf(p);
    float e   = __expf(-ap);                       // FMUL + MUFU.EX2
    float l   = __logf(1.0f + e);                  // FADD + MUFU.LG2 + FMUL
    float bce = fmaxf(p, 0.0f) + l - p * t;
    return w * bce;
}

__global__ __launch_bounds__(256) void loss_kernel(const float4* __restrict__ preds,
                                                   const int4*   __restrict__ targets,
                                                   float* __restrict__ out,
                                                   int nvec, float scale) {
    float acc = 0.0f;
    const int stride = gridDim.x * blockDim.x;
    for (int v = blockIdx.x * blockDim.x + threadIdx.x; v < nvec; v += stride) {
        float4 p = preds[v];
        int4   t = targets[v];
        int c = (v * 4) & (CCOLS - 1);             // C is a power of 2; float4 never wraps
        acc += elem_term(p.x, t.x, c + 0);
        acc += elem_term(p.y, t.y, c + 1);
        acc += elem_term(p.z, t.z, c + 2);
        acc += elem_term(p.w, t.w, c + 3);
    }
    // block reduction
#pragma unroll
    for (int o = 16; o > 0; o >>= 1) acc += __shfl_down_sync(0xffffffffu, acc, o);
    __shared__ float sw[8];
    int lane = threadIdx.x & 31, wid = threadIdx.x >> 5;
    if (lane == 0) sw[wid] = acc;
    __syncthreads();
    if (wid == 0) {
        acc = (lane < 8) ? sw[lane] : 0.0f;
#pragma unroll
        for (int o = 4; o > 0; o >>= 1) acc += __shfl_down_sync(0xffffffffu, acc, o);
        if (lane == 0) atomicAdd(out, acc * scale);
    }
}

// ---------------------------------------------------------------- launch
extern "C" void kernel_launch(void* const* d_in, const int* in_sizes, int n_in,
                              void* d_out, int out_size) {
    const float* preds   = (const float*)d_in[0];   // [8192, 2048] f32
    const int*   targets = (const int*)  d_in[1];   // [8192, 2048] i32
    const float* acc_sum = (const float*)d_in[2];   // [30, 2048]   f32
    float* out = (float*)d_out;                     // scalar loss

    // K0: zero counts + output
    zero_kernel<<<(BINS * CCOLS + 255) / 256, 256>>>(out);

    // K1: histogram (8 col-blocks x 64 row-chunks)
    dim3 hgrid(CCOLS / 256, NROWS / ROWS_PER_BLK);
    hist_kernel<<<hgrid, 256>>>(preds, targets);

    // K2: weight table
    wfac_kernel<<<CCOLS / 256, 256>>>(acc_sum);

    // K3: weighted BCE mean
    const int nvec = (NROWS * CCOLS) / 4;
    const float scale = 1.0f / (float)(NROWS * (long long)CCOLS);  // LOSS_WEIGHT = 1
    loss_kernel<<<1184, 256>>>((const float4*)preds, (const int4*)targets, out, nvec, scale);
}

// round 7
// speedup vs baseline: 1.0398x; 1.0398x over previous
#include <cuda_runtime.h>

#define NROWS 8192
#define CCOLS 2048
#define BINS  30
#define TOTF  8192.0f  /* tot = max(N,1) */
#define RPB   256      /* rows per block in fused pass */
#define TPB   128      /* threads per block = columns per block */

// Scratch (no cudaMalloc allowed): per-(bin,col) counts and bce sums.
__device__ float g_cnt[BINS * CCOLS];
__device__ float g_sum[BINS * CCOLS];

// bin = clip(floor(30*|sigmoid(p)-t|), 0, 29)
// |sigmoid(p)-t| = sigmoid(s), s = p*(1-2t) for t in {0,1}
// 30*sigmoid(s) = 15*tanh(s/2) + 15  -> single MUFU.TANH
__device__ __forceinline__ int bin_of_s(float s) {
    float u;
    asm("tanh.approx.f32 %0, %1;" : "=f"(u) : "f"(0.5f * s));
    int b = __float2int_rd(fmaf(15.0f, u, 15.0f));
    return min(max(b, 0), BINS - 1);
}

// ---------------------------------------------------------------- K0: zero scratch + out
__global__ void zero_kernel(float* out) {
    int i = blockIdx.x * blockDim.x + threadIdx.x;
    if (i < BINS * CCOLS) { g_cnt[i] = 0.0f; g_sum[i] = 0.0f; }
    if (i == 0) out[0] = 0.0f;
}

// ---------------------------------------------------------------- K1: fused histogram + BCE-sum
// Single pass over preds/targets. Each thread owns one column; per-column
// (sum,count) accumulators per bin live in shared as float2 -> conflict-free,
// no atomics, no __syncthreads (thread-private columns).
__global__ __launch_bounds__(TPB) void fused_kernel(const float* __restrict__ preds,
                                                    const int*   __restrict__ targets) {
    __shared__ float2 sh[BINS][TPB];   // 30*128*8 = 30720 B
    const int tid = threadIdx.x;
    const int c   = blockIdx.x * TPB + tid;
    const int r0  = blockIdx.y * RPB;

#pragma unroll
    for (int b = 0; b < BINS; b++) sh[b][tid] = make_float2(0.0f, 0.0f);

    const float* pp = preds   + (size_t)r0 * CCOLS + c;
    const int*   tp = targets + (size_t)r0 * CCOLS + c;

#pragma unroll 8
    for (int r = 0; r < RPB; r++) {
        float p = pp[(size_t)r * CCOLS];
        float t = (float)tp[(size_t)r * CCOLS];
        // s = p*(1-2t);  bce = softplus(p) - p*t = softplus(s)
        float s = p * fmaf(-2.0f, t, 1.0f);
        int   b = bin_of_s(s);
        float as  = fabsf(s);
        float e   = __expf(-as);
        float bce = fmaxf(s, 0.0f) + __logf(1.0f + e);
        float2 v = sh[b][tid];
        v.x += bce;
        v.y += 1.0f;
        sh[b][tid] = v;
    }

    // flush: spread, mostly-coalesced float atomics; skip empty bins
#pragma unroll
    for (int b = 0; b < BINS; b++) {
        float2 v = sh[b][tid];
        if (v.y != 0.0f) {
            atomicAdd(&g_sum[b * CCOLS + c], v.x);
            atomicAdd(&g_cnt[b * CCOLS + c], v.y);
        }
    }
}

// ---------------------------------------------------------------- K2: finalize
// loss = (1/(N*C)) * sum_c [ (TOT / max(n_c,1)) * sum_b S[b][c] / acc_new[b][c] ]
__global__ __launch_bounds__(256) void finalize_kernel(const float* __restrict__ acc_sum,
                                                       float* __restrict__ out,
                                                       float scale) {
    const int c = blockIdx.x * 256 + threadIdx.x;

    float n = 0.0f;
#pragma unroll
    for (int b = 0; b < BINS; b++) n += (g_cnt[b * CCOLS + c] >= 1.0f) ? 1.0f : 0.0f;
    float inv_n = 1.0f / fmaxf(n, 1.0f);

    float colsum = 0.0f;
#pragma unroll
    for (int b = 0; b < BINS; b++) {
        float cnt = g_cnt[b * CCOLS + c];
        if (cnt > 0.0f) {
            float accn = fmaf(0.25f, cnt, 0.75f * acc_sum[b * CCOLS + c]);
            colsum += g_sum[b * CCOLS + c] / accn;   // accn >= 0.25 when cnt>0
        }
    }
    float acc = colsum * (TOTF * inv_n) * scale;

    // block reduction -> one atomic per block
#pragma unroll
    for (int o = 16; o > 0; o >>= 1) acc += __shfl_down_sync(0xffffffffu, acc, o);
    __shared__ float sw[8];
    int lane = threadIdx.x & 31, wid = threadIdx.x >> 5;
    if (lane == 0) sw[wid] = acc;
    __syncthreads();
    if (wid == 0) {
        acc = (lane < 8) ? sw[lane] : 0.0f;
#pragma unroll
        for (int o = 4; o > 0; o >>= 1) acc += __shfl_down_sync(0xffffffffu, acc, o);
        if (lane == 0) atomicAdd(out, acc);
    }
}

// ---------------------------------------------------------------- launch
extern "C" void kernel_launch(void* const* d_in, const int* in_sizes, int n_in,
                              void* d_out, int out_size) {
    const float* preds   = (const float*)d_in[0];   // [8192, 2048] f32
    const int*   targets = (const int*)  d_in[1];   // [8192, 2048] i32
    const float* acc_sum = (const float*)d_in[2];   // [30, 2048]   f32
    float* out = (float*)d_out;                     // scalar loss

    // K0: zero scratch + output
    zero_kernel<<<(BINS * CCOLS + 255) / 256, 256>>>(out);

    // K1: single fused pass (16 col-blocks x 32 row-chunks = 512 blocks, ~1 wave)
    dim3 fgrid(CCOLS / TPB, NROWS / RPB);
    fused_kernel<<<fgrid, TPB>>>(preds, targets);

    // K2: finalize (tiny)
    const float scale = 1.0f / ((float)NROWS * (float)CCOLS);  // LOSS_WEIGHT = 1
    finalize_kernel<<<CCOLS / 256, 256>>>(acc_sum, out, scale);
}